// round 1
// baseline (speedup 1.0000x reference)
#include <cuda_runtime.h>
#include <cuda_bf16.h>

// ---------------------------------------------------------------------------
// GAT (2-layer, H=4, D=32, IN=128) on GB300.
// Strategy: per-launch CSR-by-dst build, then warp-per-node softmax+SpMM.
// ---------------------------------------------------------------------------

#define NN 50000
#define EE 800000
#define FDIM 128   // H*D = 128 for both layers
#define NHEAD 4
#define NEG_SLOPE 0.2f

// -------------------- scratch (static device globals) ----------------------
__device__ float  g_feat[NN * FDIM];    // 25.6 MB  (x@W of current layer)
__device__ float  g_h1[NN * FDIM];      // 25.6 MB  (layer-1 output)
__device__ float4 g_ee[EE];             // 12.8 MB  (edge logits -> weights, CSR order)
__device__ int    g_csr_src[EE];        //  3.2 MB  (src node per CSR slot)
__device__ int    g_cnt[NN];            // in-degree
__device__ int    g_row[NN];            // CSR row start
__device__ int    g_pos[NN];            // scatter cursor
__device__ float4 g_el[NN];             // per-node el (4 heads)
__device__ float4 g_er[NN];             // per-node er (4 heads)
__device__ int    g_bsum[64];           // scan block sums

// -------------------- CSR build --------------------------------------------
__global__ void k_zero_cnt() {
    int i = blockIdx.x * blockDim.x + threadIdx.x;
    if (i < NN) g_cnt[i] = 0;
}

__global__ void k_count(const int* __restrict__ dst) {
    int e = blockIdx.x * blockDim.x + threadIdx.x;
    if (e < EE) atomicAdd(&g_cnt[dst[e]], 1);
}

// block-level inclusive scan (chunk = 1024) -> exclusive, per-block sums
__global__ void k_scan1() {
    __shared__ int sm[1024];
    int i = blockIdx.x * 1024 + threadIdx.x;
    int v = (i < NN) ? g_cnt[i] : 0;
    sm[threadIdx.x] = v;
    __syncthreads();
#pragma unroll
    for (int off = 1; off < 1024; off <<= 1) {
        int t = (threadIdx.x >= off) ? sm[threadIdx.x - off] : 0;
        __syncthreads();
        sm[threadIdx.x] += t;
        __syncthreads();
    }
    if (i < NN) g_row[i] = sm[threadIdx.x] - v;   // exclusive within block
    if (threadIdx.x == 1023) g_bsum[blockIdx.x] = sm[1023];
}

__global__ void k_scan2(int nb) {
    if (threadIdx.x == 0) {
        int s = 0;
        for (int i = 0; i < nb; i++) { int v = g_bsum[i]; g_bsum[i] = s; s += v; }
    }
}

__global__ void k_scan3() {
    int i = blockIdx.x * blockDim.x + threadIdx.x;
    if (i < NN) {
        int v = g_row[i] + g_bsum[i >> 10];
        g_row[i] = v;
        g_pos[i] = v;
    }
}

__global__ void k_scatter(const int* __restrict__ src, const int* __restrict__ dst) {
    int e = blockIdx.x * blockDim.x + threadIdx.x;
    if (e < EE) {
        int d = dst[e];
        int p = atomicAdd(&g_pos[d], 1);
        g_csr_src[p] = src[e];
    }
}

// -------------------- GEMM: Y[N,128] = X[N,128] @ W[128,128] ----------------
#define GTM 64
#define GTK 32
__global__ void __launch_bounds__(256) k_gemm(const float* __restrict__ X,
                                              const float* __restrict__ W,
                                              float* __restrict__ Y) {
    __shared__ float Xs[GTM][GTK];
    __shared__ float Ws[GTK][FDIM];
    int t = threadIdx.x;
    int tx = t & 31, ty = t >> 5;
    int row0 = blockIdx.x * GTM;
    float acc[8][4];
#pragma unroll
    for (int i = 0; i < 8; i++)
#pragma unroll
        for (int j = 0; j < 4; j++) acc[i][j] = 0.f;

    for (int kc = 0; kc < FDIM; kc += GTK) {
#pragma unroll
        for (int i = 0; i < 8; i++) {
            int id = t + i * 256;
            int r = id >> 5, c = id & 31;
            int gr = row0 + r;
            Xs[r][c] = (gr < NN) ? X[gr * FDIM + kc + c] : 0.f;
        }
#pragma unroll
        for (int i = 0; i < 16; i++) {
            int id = t + i * 256;
            int r = id >> 7, c = id & 127;
            Ws[r][c] = W[(kc + r) * FDIM + c];
        }
        __syncthreads();
#pragma unroll
        for (int k = 0; k < GTK; k++) {
            float b0 = Ws[k][tx * 4 + 0];
            float b1 = Ws[k][tx * 4 + 1];
            float b2 = Ws[k][tx * 4 + 2];
            float b3 = Ws[k][tx * 4 + 3];
#pragma unroll
            for (int i = 0; i < 8; i++) {
                float a = Xs[ty * 8 + i][k];
                acc[i][0] += a * b0;
                acc[i][1] += a * b1;
                acc[i][2] += a * b2;
                acc[i][3] += a * b3;
            }
        }
        __syncthreads();
    }
#pragma unroll
    for (int i = 0; i < 8; i++) {
        int gr = row0 + ty * 8 + i;
        if (gr < NN) {
            float4 v = make_float4(acc[i][0], acc[i][1], acc[i][2], acc[i][3]);
            *reinterpret_cast<float4*>(&Y[gr * FDIM + tx * 4]) = v;
        }
    }
}

// -------------------- per-node attention vectors el/er ----------------------
__global__ void k_elr(const float* __restrict__ feat,
                      const float* __restrict__ al,
                      const float* __restrict__ ar) {
    int warp = (blockIdx.x * blockDim.x + threadIdx.x) >> 5;
    int lane = threadIdx.x & 31;
    if (warp >= NN) return;
    const float* f = feat + warp * FDIM;
    float vl[NHEAD], vr[NHEAD];
#pragma unroll
    for (int h = 0; h < NHEAD; h++) {
        float v = f[h * 32 + lane];
        vl[h] = v * al[h * 32 + lane];
        vr[h] = v * ar[h * 32 + lane];
    }
#pragma unroll
    for (int off = 16; off; off >>= 1) {
#pragma unroll
        for (int h = 0; h < NHEAD; h++) {
            vl[h] += __shfl_xor_sync(0xffffffffu, vl[h], off);
            vr[h] += __shfl_xor_sync(0xffffffffu, vr[h], off);
        }
    }
    if (lane == 0) {
        g_el[warp] = make_float4(vl[0], vl[1], vl[2], vl[3]);
        g_er[warp] = make_float4(vr[0], vr[1], vr[2], vr[3]);
    }
}

// -------------------- warp-per-node softmax + SpMM --------------------------
__device__ __forceinline__ float lrelu(float x) { return x > 0.f ? x : NEG_SLOPE * x; }
__device__ __forceinline__ float elu1(float x)  { return x > 0.f ? x : (__expf(x) - 1.f); }

// MODE 1: layer1 -> elu, write 128 feats to g_h1
// MODE 2: layer2 -> head-mean, write 32 feats to out
template <int MODE>
__global__ void __launch_bounds__(256) k_agg(const float* __restrict__ feat,
                                             const float* __restrict__ resid,
                                             const float* __restrict__ bias,
                                             float* __restrict__ out) {
    int node = blockIdx.x * (blockDim.x >> 5) + (threadIdx.x >> 5);
    int lane = threadIdx.x & 31;
    if (node >= NN) return;

    int base = g_row[node];
    int deg  = g_cnt[node];
    float4 er4 = g_er[node];

    // ---- pass 1: logits + running max (lane-per-edge) ----
    float mx = -1e30f, my = -1e30f, mz = -1e30f, mw = -1e30f;
    for (int j = lane; j < deg; j += 32) {
        int s = g_csr_src[base + j];
        float4 l4 = g_el[s];
        float4 e4;
        e4.x = lrelu(l4.x + er4.x);
        e4.y = lrelu(l4.y + er4.y);
        e4.z = lrelu(l4.z + er4.z);
        e4.w = lrelu(l4.w + er4.w);
        g_ee[base + j] = e4;
        mx = fmaxf(mx, e4.x); my = fmaxf(my, e4.y);
        mz = fmaxf(mz, e4.z); mw = fmaxf(mw, e4.w);
    }
#pragma unroll
    for (int off = 16; off; off >>= 1) {
        mx = fmaxf(mx, __shfl_xor_sync(0xffffffffu, mx, off));
        my = fmaxf(my, __shfl_xor_sync(0xffffffffu, my, off));
        mz = fmaxf(mz, __shfl_xor_sync(0xffffffffu, mz, off));
        mw = fmaxf(mw, __shfl_xor_sync(0xffffffffu, mw, off));
    }

    // ---- pass 2: exp + denom (lane-per-edge) ----
    float sx = 0.f, sy = 0.f, sz = 0.f, sw = 0.f;
    for (int j = lane; j < deg; j += 32) {
        float4 e4 = g_ee[base + j];
        float4 w4;
        w4.x = __expf(e4.x - mx);
        w4.y = __expf(e4.y - my);
        w4.z = __expf(e4.z - mz);
        w4.w = __expf(e4.w - mw);
        g_ee[base + j] = w4;
        sx += w4.x; sy += w4.y; sz += w4.z; sw += w4.w;
    }
#pragma unroll
    for (int off = 16; off; off >>= 1) {
        sx += __shfl_xor_sync(0xffffffffu, sx, off);
        sy += __shfl_xor_sync(0xffffffffu, sy, off);
        sz += __shfl_xor_sync(0xffffffffu, sz, off);
        sw += __shfl_xor_sync(0xffffffffu, sw, off);
    }
    float invx = 1.f / fmaxf(sx, 1e-9f);
    float invy = 1.f / fmaxf(sy, 1e-9f);
    float invz = 1.f / fmaxf(sz, 1e-9f);
    float invw = 1.f / fmaxf(sw, 1e-9f);

    // ---- pass 3: weighted aggregation (whole warp per edge, 2x unrolled) ----
    float a0 = 0.f, a1 = 0.f, a2 = 0.f, a3 = 0.f;
    int j = 0;
    for (; j + 1 < deg; j += 2) {
        float4 w0 = g_ee[base + j];
        float4 w1 = g_ee[base + j + 1];
        int s0 = g_csr_src[base + j];
        int s1 = g_csr_src[base + j + 1];
        const float* f0 = g_feat + s0 * FDIM + lane;
        const float* f1 = g_feat + s1 * FDIM + lane;
        float v00 = f0[0], v01 = f0[32], v02 = f0[64], v03 = f0[96];
        float v10 = f1[0], v11 = f1[32], v12 = f1[64], v13 = f1[96];
        a0 += w0.x * v00 + w1.x * v10;
        a1 += w0.y * v01 + w1.y * v11;
        a2 += w0.z * v02 + w1.z * v12;
        a3 += w0.w * v03 + w1.w * v13;
    }
    if (j < deg) {
        float4 w0 = g_ee[base + j];
        int s0 = g_csr_src[base + j];
        const float* f0 = g_feat + s0 * FDIM + lane;
        a0 += w0.x * f0[0];
        a1 += w0.y * f0[32];
        a2 += w0.z * f0[64];
        a3 += w0.w * f0[96];
    }
    (void)feat;  // g_feat used directly

    float r0 = a0 * invx + resid[node * FDIM + 0  + lane] + bias[0  + lane];
    float r1 = a1 * invy + resid[node * FDIM + 32 + lane] + bias[32 + lane];
    float r2 = a2 * invz + resid[node * FDIM + 64 + lane] + bias[64 + lane];
    float r3 = a3 * invw + resid[node * FDIM + 96 + lane] + bias[96 + lane];

    if (MODE == 1) {
        out[node * FDIM + 0  + lane] = elu1(r0);
        out[node * FDIM + 32 + lane] = elu1(r1);
        out[node * FDIM + 64 + lane] = elu1(r2);
        out[node * FDIM + 96 + lane] = elu1(r3);
    } else {
        out[node * 32 + lane] = 0.25f * (r0 + r1 + r2 + r3);
    }
}

// -------------------- launch ------------------------------------------------
extern "C" void kernel_launch(void* const* d_in, const int* in_sizes, int n_in,
                              void* d_out, int out_size) {
    const float* x   = (const float*)d_in[0];
    const float* W1  = (const float*)d_in[1];
    const float* al1 = (const float*)d_in[2];
    const float* ar1 = (const float*)d_in[3];
    const float* b1  = (const float*)d_in[4];
    const float* W2  = (const float*)d_in[5];
    const float* al2 = (const float*)d_in[6];
    const float* ar2 = (const float*)d_in[7];
    const float* b2  = (const float*)d_in[8];
    const int*   src = (const int*)d_in[9];
    const int*   dst = (const int*)d_in[10];
    float* out = (float*)d_out;

    float* feat = nullptr; float* h1 = nullptr;
    cudaGetSymbolAddress((void**)&feat, g_feat);
    cudaGetSymbolAddress((void**)&h1, g_h1);

    const int TB = 256;
    int nblkN = (NN + TB - 1) / TB;
    int nblkE = (EE + TB - 1) / TB;
    int nScan = (NN + 1023) / 1024;          // 49
    int nWarpBlk = (NN + 7) / 8;             // 8 warps/block
    int nGemm = (NN + GTM - 1) / GTM;        // 782

    // ---- CSR build (once; edges shared by both layers) ----
    k_zero_cnt<<<nblkN, TB>>>();
    k_count<<<nblkE, TB>>>(dst);
    k_scan1<<<nScan, 1024>>>();
    k_scan2<<<1, 32>>>(nScan);
    k_scan3<<<nblkN, TB>>>();
    k_scatter<<<nblkE, TB>>>(src, dst);

    // ---- layer 1 ----
    k_gemm<<<nGemm, 256>>>(x, W1, feat);
    k_elr<<<nWarpBlk, 256>>>(feat, al1, ar1);
    k_agg<1><<<nWarpBlk, 256>>>(feat, x, b1, h1);

    // ---- layer 2 ----
    k_gemm<<<nGemm, 256>>>(h1, W2, feat);
    k_elr<<<nWarpBlk, 256>>>(feat, al2, ar2);
    k_agg<2><<<nWarpBlk, 256>>>(feat, h1, b2, out);
}

// round 3
// speedup vs baseline: 1.3342x; 1.3342x over previous
#include <cuda_runtime.h>
#include <cuda_fp16.h>
#include <cuda_bf16.h>

// ---------------------------------------------------------------------------
// GAT (2-layer, H=4, D=32, IN=128) on GB300, round 2.
//  - f32x2 packed-FFMA GEMM with fused el/er epilogue + fp16 feature emit
//  - CSR-by-dst build, warp-per-node softmax (no-max) + fp16 SpMM gather
// ---------------------------------------------------------------------------

#define NN 50000
#define EE 800000
#define FDIM 128
#define NHEAD 4
#define NEG_SLOPE 0.2f

typedef unsigned long long ull;

// -------------------- scratch (static device globals) ----------------------
__device__ __half g_feat_h[NN * FDIM];   // 12.8 MB  fp16 features, head-interleaved
__device__ float  g_h1[NN * FDIM];       // 25.6 MB  layer-1 output (fp32)
__device__ float4 g_ee[EE];              // 12.8 MB  edge weights (CSR order)
__device__ int    g_csr_src[EE];         //  3.2 MB
__device__ int    g_cnt[NN];
__device__ int    g_row[NN];
__device__ int    g_pos[NN];
__device__ float  g_el[NN * 4];
__device__ float  g_er[NN * 4];
__device__ int    g_bsum[64];

// -------------------- f32x2 helpers -----------------------------------------
__device__ __forceinline__ ull pk2(float lo, float hi) {
    ull r; asm("mov.b64 %0, {%1, %2};" : "=l"(r) : "f"(lo), "f"(hi)); return r;
}
__device__ __forceinline__ void ffma2(ull& d, ull a, ull b) {
    asm("fma.rn.f32x2 %0, %1, %2, %0;" : "+l"(d) : "l"(a), "l"(b));
}
__device__ __forceinline__ float2 unpk(ull v) {
    float2 f; asm("mov.b64 {%0, %1}, %2;" : "=f"(f.x), "=f"(f.y) : "l"(v)); return f;
}

// -------------------- CSR build --------------------------------------------
__global__ void k_zero_cnt() {
    int i = blockIdx.x * blockDim.x + threadIdx.x;
    if (i < NN) g_cnt[i] = 0;
}

__global__ void k_count(const int* __restrict__ dst) {
    int e = blockIdx.x * blockDim.x + threadIdx.x;
    if (e < EE) atomicAdd(&g_cnt[dst[e]], 1);
}

__global__ void k_scan1() {
    __shared__ int sm[1024];
    int i = blockIdx.x * 1024 + threadIdx.x;
    int v = (i < NN) ? g_cnt[i] : 0;
    sm[threadIdx.x] = v;
    __syncthreads();
#pragma unroll
    for (int off = 1; off < 1024; off <<= 1) {
        int t = (threadIdx.x >= off) ? sm[threadIdx.x - off] : 0;
        __syncthreads();
        sm[threadIdx.x] += t;
        __syncthreads();
    }
    if (i < NN) g_row[i] = sm[threadIdx.x] - v;
    if (threadIdx.x == 1023) g_bsum[blockIdx.x] = sm[1023];
}

// parallel exclusive scan of <=64 block sums (1 block, 64 threads)
__global__ void k_scan2(int nb) {
    int t = threadIdx.x;
    int v = (t < nb) ? g_bsum[t] : 0;
    int lane = t & 31, w = t >> 5;
    int x = v;
#pragma unroll
    for (int off = 1; off < 32; off <<= 1) {
        int y = __shfl_up_sync(0xffffffffu, x, off);
        if (lane >= off) x += y;
    }
    __shared__ int ws[2];
    if (lane == 31) ws[w] = x;
    __syncthreads();
    if (w == 1) x += ws[0];
    if (t < nb) g_bsum[t] = x - v;   // exclusive
}

__global__ void k_scan3() {
    int i = blockIdx.x * blockDim.x + threadIdx.x;
    if (i < NN) {
        int v = g_row[i] + g_bsum[i >> 10];
        g_row[i] = v;
        g_pos[i] = v;
    }
}

__global__ void k_scatter(const int* __restrict__ src, const int* __restrict__ dst) {
    int e = blockIdx.x * blockDim.x + threadIdx.x;
    if (e < EE) {
        int d = dst[e];
        int p = atomicAdd(&g_pos[d], 1);
        g_csr_src[p] = src[e];
    }
}

// -------------------- fused GEMM + el/er + fp16 emit ------------------------
// Y = X[N,128] @ W[128,128]; emits g_feat_h (head-interleaved fp16) and g_el/g_er.
#define GTM 64
#define GTK 32
__global__ void __launch_bounds__(256) k_gemm_fused(const float* __restrict__ X,
                                                    const float* __restrict__ W,
                                                    const float* __restrict__ al,
                                                    const float* __restrict__ ar) {
    __shared__ float Xs[GTK][GTM + 2];            // transposed, padded (8B-aligned rows)
    __shared__ float Ws[GTK][FDIM];
    __shared__ __align__(16) __half Hs[GTM][FDIM];

    int t = threadIdx.x;
    int tx = t & 31, ty = t >> 5;
    int row0 = blockIdx.x * GTM;

    ull acc[4][4];
#pragma unroll
    for (int p = 0; p < 4; p++)
#pragma unroll
        for (int c = 0; c < 4; c++) acc[p][c] = 0ull;

    for (int kc = 0; kc < FDIM; kc += GTK) {
#pragma unroll
        for (int i = 0; i < 8; i++) {
            int id = t + i * 256;
            int r = id >> 5, c = id & 31;
            int gr = row0 + r;
            Xs[c][r] = (gr < NN) ? X[gr * FDIM + kc + c] : 0.f;
        }
#pragma unroll
        for (int i = 0; i < 16; i++) {
            int id = t + i * 256;
            int r = id >> 7, c = id & 127;
            Ws[r][c] = W[(kc + r) * FDIM + c];
        }
        __syncthreads();
#pragma unroll
        for (int k = 0; k < GTK; k++) {
            float4 bv = *reinterpret_cast<const float4*>(&Ws[k][tx * 4]);
            ull b0 = pk2(bv.x, bv.x), b1 = pk2(bv.y, bv.y);
            ull b2 = pk2(bv.z, bv.z), b3 = pk2(bv.w, bv.w);
#pragma unroll
            for (int p = 0; p < 4; p++) {
                ull a = *reinterpret_cast<const ull*>(&Xs[k][ty * 8 + p * 2]);
                ffma2(acc[p][0], a, b0);
                ffma2(acc[p][1], a, b1);
                ffma2(acc[p][2], a, b2);
                ffma2(acc[p][3], a, b3);
            }
        }
        __syncthreads();
    }

    // epilogue: fp16 emit (permuted) + el/er
    float4 alv = *reinterpret_cast<const float4*>(&al[tx * 4]);
    float4 arv = *reinterpret_cast<const float4*>(&ar[tx * 4]);
    int head = tx >> 3;
#pragma unroll
    for (int p = 0; p < 4; p++) {
        float2 v0 = unpk(acc[p][0]);
        float2 v1 = unpk(acc[p][1]);
        float2 v2 = unpk(acc[p][2]);
        float2 v3 = unpk(acc[p][3]);
        int r0 = ty * 8 + p * 2, r1 = r0 + 1;
        // permuted pos for col = tx*4+c : pos = (col&31)*4 + (col>>5)
#pragma unroll
        for (int c = 0; c < 4; c++) {
            int col = tx * 4 + c;
            int pos = ((col & 31) << 2) | (col >> 5);
            float lo = (c == 0) ? v0.x : (c == 1) ? v1.x : (c == 2) ? v2.x : v3.x;
            float hi = (c == 0) ? v0.y : (c == 1) ? v1.y : (c == 2) ? v2.y : v3.y;
            Hs[r0][pos] = __float2half(lo);
            Hs[r1][pos] = __float2half(hi);
        }
        float pl0 = v0.x * alv.x + v1.x * alv.y + v2.x * alv.z + v3.x * alv.w;
        float pr0 = v0.x * arv.x + v1.x * arv.y + v2.x * arv.z + v3.x * arv.w;
        float pl1 = v0.y * alv.x + v1.y * alv.y + v2.y * alv.z + v3.y * alv.w;
        float pr1 = v0.y * arv.x + v1.y * arv.y + v2.y * arv.z + v3.y * arv.w;
#pragma unroll
        for (int off = 4; off; off >>= 1) {
            pl0 += __shfl_xor_sync(0xffffffffu, pl0, off);
            pr0 += __shfl_xor_sync(0xffffffffu, pr0, off);
            pl1 += __shfl_xor_sync(0xffffffffu, pl1, off);
            pr1 += __shfl_xor_sync(0xffffffffu, pr1, off);
        }
        if ((tx & 7) == 0) {
            if (row0 + r0 < NN) {
                g_el[(row0 + r0) * 4 + head] = pl0;
                g_er[(row0 + r0) * 4 + head] = pr0;
            }
            if (row0 + r1 < NN) {
                g_el[(row0 + r1) * 4 + head] = pl1;
                g_er[(row0 + r1) * 4 + head] = pr1;
            }
        }
    }
    __syncthreads();
    // coalesced fp16 write-out: 64 rows x 256B
#pragma unroll
    for (int i = t; i < GTM * 16; i += 256) {
        int r = i >> 4, c = i & 15;
        int gr = row0 + r;
        if (gr < NN)
            reinterpret_cast<uint4*>(g_feat_h + (size_t)gr * FDIM)[c] =
                reinterpret_cast<const uint4*>(&Hs[r][0])[c];
    }
}

// -------------------- warp-per-node softmax + SpMM --------------------------
__device__ __forceinline__ float lrelu(float x) { return x > 0.f ? x : NEG_SLOPE * x; }
__device__ __forceinline__ float elu1(float x)  { return x > 0.f ? x : (__expf(x) - 1.f); }

// MODE 1: layer1 -> elu, write 128 feats (fp32) to g_h1
// MODE 2: layer2 -> head-mean, write 32 feats to out
template <int MODE>
__global__ void __launch_bounds__(256) k_agg(const float* __restrict__ resid,
                                             const float* __restrict__ bias,
                                             float* __restrict__ out) {
    int node = blockIdx.x * (blockDim.x >> 5) + (threadIdx.x >> 5);
    int lane = threadIdx.x & 31;
    if (node >= NN) return;

    int base = g_row[node];
    int deg  = g_cnt[node];
    float4 er4 = reinterpret_cast<const float4*>(g_er)[node];

    // ---- pass 1: w = exp(lrelu(el+er)) + denom (lane-per-edge, no max) ----
    float sx = 0.f, sy = 0.f, sz = 0.f, sw = 0.f;
    for (int j = lane; j < deg; j += 32) {
        int s = g_csr_src[base + j];
        float4 l4 = reinterpret_cast<const float4*>(g_el)[s];
        float4 w4;
        w4.x = __expf(lrelu(l4.x + er4.x));
        w4.y = __expf(lrelu(l4.y + er4.y));
        w4.z = __expf(lrelu(l4.z + er4.z));
        w4.w = __expf(lrelu(l4.w + er4.w));
        g_ee[base + j] = w4;
        sx += w4.x; sy += w4.y; sz += w4.z; sw += w4.w;
    }
#pragma unroll
    for (int off = 16; off; off >>= 1) {
        sx += __shfl_xor_sync(0xffffffffu, sx, off);
        sy += __shfl_xor_sync(0xffffffffu, sy, off);
        sz += __shfl_xor_sync(0xffffffffu, sz, off);
        sw += __shfl_xor_sync(0xffffffffu, sw, off);
    }
    float invx = 1.f / fmaxf(sx, 1e-9f);
    float invy = 1.f / fmaxf(sy, 1e-9f);
    float invz = 1.f / fmaxf(sz, 1e-9f);
    float invw = 1.f / fmaxf(sw, 1e-9f);

    // ---- pass 2: weighted aggregation (whole warp per edge, 2x unrolled) ----
    float a0 = 0.f, a1 = 0.f, a2 = 0.f, a3 = 0.f;
    int j = 0;
    for (; j + 1 < deg; j += 2) {
        float4 w0 = g_ee[base + j];
        float4 w1 = g_ee[base + j + 1];
        int s0 = g_csr_src[base + j];
        int s1 = g_csr_src[base + j + 1];
        uint2 u0 = *reinterpret_cast<const uint2*>(g_feat_h + (size_t)s0 * FDIM + lane * 4);
        uint2 u1 = *reinterpret_cast<const uint2*>(g_feat_h + (size_t)s1 * FDIM + lane * 4);
        float2 f00 = __half22float2(*reinterpret_cast<__half2*>(&u0.x));
        float2 f01 = __half22float2(*reinterpret_cast<__half2*>(&u0.y));
        float2 f10 = __half22float2(*reinterpret_cast<__half2*>(&u1.x));
        float2 f11 = __half22float2(*reinterpret_cast<__half2*>(&u1.y));
        a0 += w0.x * f00.x + w1.x * f10.x;
        a1 += w0.y * f00.y + w1.y * f10.y;
        a2 += w0.z * f01.x + w1.z * f11.x;
        a3 += w0.w * f01.y + w1.w * f11.y;
    }
    if (j < deg) {
        float4 w0 = g_ee[base + j];
        int s0 = g_csr_src[base + j];
        uint2 u0 = *reinterpret_cast<const uint2*>(g_feat_h + (size_t)s0 * FDIM + lane * 4);
        float2 f00 = __half22float2(*reinterpret_cast<__half2*>(&u0.x));
        float2 f01 = __half22float2(*reinterpret_cast<__half2*>(&u0.y));
        a0 += w0.x * f00.x;
        a1 += w0.y * f00.y;
        a2 += w0.z * f01.x;
        a3 += w0.w * f01.y;
    }

    float r0 = a0 * invx + resid[node * FDIM + 0  + lane] + bias[0  + lane];
    float r1 = a1 * invy + resid[node * FDIM + 32 + lane] + bias[32 + lane];
    float r2 = a2 * invz + resid[node * FDIM + 64 + lane] + bias[64 + lane];
    float r3 = a3 * invw + resid[node * FDIM + 96 + lane] + bias[96 + lane];

    if (MODE == 1) {
        out[node * FDIM + 0  + lane] = elu1(r0);
        out[node * FDIM + 32 + lane] = elu1(r1);
        out[node * FDIM + 64 + lane] = elu1(r2);
        out[node * FDIM + 96 + lane] = elu1(r3);
    } else {
        out[node * 32 + lane] = 0.25f * (r0 + r1 + r2 + r3);
    }
}

// -------------------- launch ------------------------------------------------
extern "C" void kernel_launch(void* const* d_in, const int* in_sizes, int n_in,
                              void* d_out, int out_size) {
    const float* x   = (const float*)d_in[0];
    const float* W1  = (const float*)d_in[1];
    const float* al1 = (const float*)d_in[2];
    const float* ar1 = (const float*)d_in[3];
    const float* b1  = (const float*)d_in[4];
    const float* W2  = (const float*)d_in[5];
    const float* al2 = (const float*)d_in[6];
    const float* ar2 = (const float*)d_in[7];
    const float* b2  = (const float*)d_in[8];
    const int*   src = (const int*)d_in[9];
    const int*   dst = (const int*)d_in[10];
    float* out = (float*)d_out;

    float* h1 = nullptr;
    cudaGetSymbolAddress((void**)&h1, g_h1);

    const int TB = 256;
    int nblkN = (NN + TB - 1) / TB;
    int nblkE = (EE + TB - 1) / TB;
    int nScan = (NN + 1023) / 1024;          // 49
    int nWarpBlk = (NN + 7) / 8;             // 8 warps/block
    int nGemm = (NN + GTM - 1) / GTM;        // 782

    // ---- CSR build (once; shared by both layers) ----
    k_zero_cnt<<<nblkN, TB>>>();
    k_count<<<nblkE, TB>>>(dst);
    k_scan1<<<nScan, 1024>>>();
    k_scan2<<<1, 64>>>(nScan);
    k_scan3<<<nblkN, TB>>>();
    k_scatter<<<nblkE, TB>>>(src, dst);

    // ---- layer 1 ----
    k_gemm_fused<<<nGemm, 256>>>(x, W1, al1, ar1);
    k_agg<1><<<nWarpBlk, 256>>>(x, b1, h1);

    // ---- layer 2 ----
    k_gemm_fused<<<nGemm, 256>>>(h1, W2, al2, ar2);
    k_agg<2><<<nWarpBlk, 256>>>(h1, b2, out);
}

// round 4
// speedup vs baseline: 1.3498x; 1.0117x over previous
#include <cuda_runtime.h>
#include <cuda_fp16.h>
#include <cuda_bf16.h>

// ---------------------------------------------------------------------------
// GAT (2-layer, H=4, D=32, IN=128) on GB300, round 4.
//  - f32x2 packed-FFMA GEMM with fused el/er epilogue + fp16 feature emit
//  - CSR-by-dst build; SINGLE-PASS warp-per-node softmax+SpMM
//    (unnormalized accumulate, divide by denom at the end; no edge-weight
//     array in gmem at all)
// ---------------------------------------------------------------------------

#define NN 50000
#define EE 800000
#define FDIM 128
#define NHEAD 4
#define NEG_SLOPE 0.2f

typedef unsigned long long ull;

// -------------------- scratch (static device globals) ----------------------
__device__ __half g_feat_h[NN * FDIM];   // 12.8 MB  fp16 features, head-interleaved
__device__ float  g_h1[NN * FDIM];       // 25.6 MB  layer-1 output (fp32)
__device__ int    g_csr_src[EE];         //  3.2 MB
__device__ int    g_cnt[NN];
__device__ int    g_row[NN];
__device__ int    g_pos[NN];
__device__ float  g_el[NN * 4];
__device__ float  g_er[NN * 4];
__device__ int    g_bsum[64];

// -------------------- f32x2 helpers -----------------------------------------
__device__ __forceinline__ ull pk2(float lo, float hi) {
    ull r; asm("mov.b64 %0, {%1, %2};" : "=l"(r) : "f"(lo), "f"(hi)); return r;
}
__device__ __forceinline__ void ffma2(ull& d, ull a, ull b) {
    asm("fma.rn.f32x2 %0, %1, %2, %0;" : "+l"(d) : "l"(a), "l"(b));
}
__device__ __forceinline__ float2 unpk(ull v) {
    float2 f; asm("mov.b64 {%0, %1}, %2;" : "=f"(f.x), "=f"(f.y) : "l"(v)); return f;
}

// -------------------- CSR build --------------------------------------------
__global__ void k_zero_cnt() {
    int i = blockIdx.x * blockDim.x + threadIdx.x;
    if (i < NN) g_cnt[i] = 0;
}

__global__ void k_count(const int* __restrict__ dst) {
    int e = blockIdx.x * blockDim.x + threadIdx.x;
    if (e < EE) atomicAdd(&g_cnt[dst[e]], 1);
}

__global__ void k_scan1() {
    __shared__ int sm[1024];
    int i = blockIdx.x * 1024 + threadIdx.x;
    int v = (i < NN) ? g_cnt[i] : 0;
    sm[threadIdx.x] = v;
    __syncthreads();
#pragma unroll
    for (int off = 1; off < 1024; off <<= 1) {
        int t = (threadIdx.x >= off) ? sm[threadIdx.x - off] : 0;
        __syncthreads();
        sm[threadIdx.x] += t;
        __syncthreads();
    }
    if (i < NN) g_row[i] = sm[threadIdx.x] - v;
    if (threadIdx.x == 1023) g_bsum[blockIdx.x] = sm[1023];
}

// parallel exclusive scan of <=64 block sums (1 block, 64 threads)
__global__ void k_scan2(int nb) {
    int t = threadIdx.x;
    int v = (t < nb) ? g_bsum[t] : 0;
    int lane = t & 31, w = t >> 5;
    int x = v;
#pragma unroll
    for (int off = 1; off < 32; off <<= 1) {
        int y = __shfl_up_sync(0xffffffffu, x, off);
        if (lane >= off) x += y;
    }
    __shared__ int ws[2];
    if (lane == 31) ws[w] = x;
    __syncthreads();
    if (w == 1) x += ws[0];
    if (t < nb) g_bsum[t] = x - v;   // exclusive
}

__global__ void k_scan3() {
    int i = blockIdx.x * blockDim.x + threadIdx.x;
    if (i < NN) {
        int v = g_row[i] + g_bsum[i >> 10];
        g_row[i] = v;
        g_pos[i] = v;
    }
}

__global__ void k_scatter(const int* __restrict__ src, const int* __restrict__ dst) {
    int e = blockIdx.x * blockDim.x + threadIdx.x;
    if (e < EE) {
        int d = dst[e];
        int p = atomicAdd(&g_pos[d], 1);
        g_csr_src[p] = src[e];
    }
}

// -------------------- fused GEMM + el/er + fp16 emit ------------------------
// Y = X[N,128] @ W[128,128]; emits g_feat_h (head-interleaved fp16) and g_el/g_er.
#define GTM 64
#define GTK 32
__global__ void __launch_bounds__(256) k_gemm_fused(const float* __restrict__ X,
                                                    const float* __restrict__ W,
                                                    const float* __restrict__ al,
                                                    const float* __restrict__ ar) {
    __shared__ float Xs[GTK][GTM + 2];            // transposed, padded
    __shared__ float Ws[GTK][FDIM];
    __shared__ __align__(16) __half Hs[GTM][FDIM];

    int t = threadIdx.x;
    int tx = t & 31, ty = t >> 5;
    int row0 = blockIdx.x * GTM;

    ull acc[4][4];
#pragma unroll
    for (int p = 0; p < 4; p++)
#pragma unroll
        for (int c = 0; c < 4; c++) acc[p][c] = 0ull;

    for (int kc = 0; kc < FDIM; kc += GTK) {
#pragma unroll
        for (int i = 0; i < 8; i++) {
            int id = t + i * 256;
            int r = id >> 5, c = id & 31;
            int gr = row0 + r;
            Xs[c][r] = (gr < NN) ? X[gr * FDIM + kc + c] : 0.f;
        }
#pragma unroll
        for (int i = 0; i < 16; i++) {
            int id = t + i * 256;
            int r = id >> 7, c = id & 127;
            Ws[r][c] = W[(kc + r) * FDIM + c];
        }
        __syncthreads();
#pragma unroll
        for (int k = 0; k < GTK; k++) {
            float4 bv = *reinterpret_cast<const float4*>(&Ws[k][tx * 4]);
            ull b0 = pk2(bv.x, bv.x), b1 = pk2(bv.y, bv.y);
            ull b2 = pk2(bv.z, bv.z), b3 = pk2(bv.w, bv.w);
#pragma unroll
            for (int p = 0; p < 4; p++) {
                ull a = *reinterpret_cast<const ull*>(&Xs[k][ty * 8 + p * 2]);
                ffma2(acc[p][0], a, b0);
                ffma2(acc[p][1], a, b1);
                ffma2(acc[p][2], a, b2);
                ffma2(acc[p][3], a, b3);
            }
        }
        __syncthreads();
    }

    // epilogue: fp16 emit (head-interleaved) + el/er partial dots
    float4 alv = *reinterpret_cast<const float4*>(&al[tx * 4]);
    float4 arv = *reinterpret_cast<const float4*>(&ar[tx * 4]);
    int head = tx >> 3;
#pragma unroll
    for (int p = 0; p < 4; p++) {
        float2 v0 = unpk(acc[p][0]);
        float2 v1 = unpk(acc[p][1]);
        float2 v2 = unpk(acc[p][2]);
        float2 v3 = unpk(acc[p][3]);
        int r0 = ty * 8 + p * 2, r1 = r0 + 1;
#pragma unroll
        for (int c = 0; c < 4; c++) {
            int col = tx * 4 + c;
            int pos = ((col & 31) << 2) | (col >> 5);   // head-interleave
            float lo = (c == 0) ? v0.x : (c == 1) ? v1.x : (c == 2) ? v2.x : v3.x;
            float hi = (c == 0) ? v0.y : (c == 1) ? v1.y : (c == 2) ? v2.y : v3.y;
            Hs[r0][pos] = __float2half(lo);
            Hs[r1][pos] = __float2half(hi);
        }
        float pl0 = v0.x * alv.x + v1.x * alv.y + v2.x * alv.z + v3.x * alv.w;
        float pr0 = v0.x * arv.x + v1.x * arv.y + v2.x * arv.z + v3.x * arv.w;
        float pl1 = v0.y * alv.x + v1.y * alv.y + v2.y * alv.z + v3.y * alv.w;
        float pr1 = v0.y * arv.x + v1.y * arv.y + v2.y * arv.z + v3.y * arv.w;
#pragma unroll
        for (int off = 4; off; off >>= 1) {
            pl0 += __shfl_xor_sync(0xffffffffu, pl0, off);
            pr0 += __shfl_xor_sync(0xffffffffu, pr0, off);
            pl1 += __shfl_xor_sync(0xffffffffu, pl1, off);
            pr1 += __shfl_xor_sync(0xffffffffu, pr1, off);
        }
        if ((tx & 7) == 0) {
            if (row0 + r0 < NN) {
                g_el[(row0 + r0) * 4 + head] = pl0;
                g_er[(row0 + r0) * 4 + head] = pr0;
            }
            if (row0 + r1 < NN) {
                g_el[(row0 + r1) * 4 + head] = pl1;
                g_er[(row0 + r1) * 4 + head] = pr1;
            }
        }
    }
    __syncthreads();
#pragma unroll
    for (int i = t; i < GTM * 16; i += 256) {
        int r = i >> 4, c = i & 15;
        int gr = row0 + r;
        if (gr < NN)
            reinterpret_cast<uint4*>(g_feat_h + (size_t)gr * FDIM)[c] =
                reinterpret_cast<const uint4*>(&Hs[r][0])[c];
    }
}

// -------------------- single-pass warp-per-node softmax + SpMM --------------
__device__ __forceinline__ float lrelu(float x) { return x > 0.f ? x : NEG_SLOPE * x; }
__device__ __forceinline__ float elu1(float x)  { return x > 0.f ? x : (__expf(x) - 1.f); }

#define AGG_WARPS 8

// MODE 1: layer1 -> elu, write 128 feats (fp32) to g_h1
// MODE 2: layer2 -> head-mean, write 32 feats to out
template <int MODE>
__global__ void __launch_bounds__(AGG_WARPS * 32) k_agg(const float* __restrict__ resid,
                                                        const float* __restrict__ bias,
                                                        float* __restrict__ out) {
    __shared__ __align__(16) float4 sm_w[AGG_WARPS][33];
    __shared__ int sm_s[AGG_WARPS][32];

    int wid  = threadIdx.x >> 5;
    int lane = threadIdx.x & 31;
    int node = blockIdx.x * AGG_WARPS + wid;
    if (node >= NN) return;

    int base = g_row[node];
    int deg  = g_cnt[node];
    float4 er4 = reinterpret_cast<const float4*>(g_er)[node];

    float sx = 0.f, sy = 0.f, sz = 0.f, sw = 0.f;   // per-lane denom partials
    float a0 = 0.f, a1 = 0.f, a2 = 0.f, a3 = 0.f;   // per-lane feature accums

    for (int c0 = 0; c0 < deg; c0 += 32) {
        int m = deg - c0; if (m > 32) m = 32;
        // stage chunk: lane j computes (s_j, w4_j)
        if (lane < m) {
            int s = g_csr_src[base + c0 + lane];
            float4 l4 = reinterpret_cast<const float4*>(g_el)[s];
            float4 w4;
            w4.x = __expf(lrelu(l4.x + er4.x));
            w4.y = __expf(lrelu(l4.y + er4.y));
            w4.z = __expf(lrelu(l4.z + er4.z));
            w4.w = __expf(lrelu(l4.w + er4.w));
            sx += w4.x; sy += w4.y; sz += w4.z; sw += w4.w;
            sm_s[wid][lane] = s;
            sm_w[wid][lane] = w4;
        }
        __syncwarp();
        // warp-cooperative gather: broadcast (s_j, w4_j) from smem
        int j = 0;
        for (; j + 1 < m; j += 2) {
            int s0 = sm_s[wid][j];
            int s1 = sm_s[wid][j + 1];
            float4 w0 = sm_w[wid][j];
            float4 w1 = sm_w[wid][j + 1];
            uint2 u0 = *reinterpret_cast<const uint2*>(g_feat_h + (size_t)s0 * FDIM + lane * 4);
            uint2 u1 = *reinterpret_cast<const uint2*>(g_feat_h + (size_t)s1 * FDIM + lane * 4);
            float2 f00 = __half22float2(*reinterpret_cast<__half2*>(&u0.x));
            float2 f01 = __half22float2(*reinterpret_cast<__half2*>(&u0.y));
            float2 f10 = __half22float2(*reinterpret_cast<__half2*>(&u1.x));
            float2 f11 = __half22float2(*reinterpret_cast<__half2*>(&u1.y));
            a0 += w0.x * f00.x + w1.x * f10.x;
            a1 += w0.y * f00.y + w1.y * f10.y;
            a2 += w0.z * f01.x + w1.z * f11.x;
            a3 += w0.w * f01.y + w1.w * f11.y;
        }
        if (j < m) {
            int s0 = sm_s[wid][j];
            float4 w0 = sm_w[wid][j];
            uint2 u0 = *reinterpret_cast<const uint2*>(g_feat_h + (size_t)s0 * FDIM + lane * 4);
            float2 f00 = __half22float2(*reinterpret_cast<__half2*>(&u0.x));
            float2 f01 = __half22float2(*reinterpret_cast<__half2*>(&u0.y));
            a0 += w0.x * f00.x;
            a1 += w0.y * f00.y;
            a2 += w0.z * f01.x;
            a3 += w0.w * f01.y;
        }
        __syncwarp();
    }

    // warp-reduce denom
#pragma unroll
    for (int off = 16; off; off >>= 1) {
        sx += __shfl_xor_sync(0xffffffffu, sx, off);
        sy += __shfl_xor_sync(0xffffffffu, sy, off);
        sz += __shfl_xor_sync(0xffffffffu, sz, off);
        sw += __shfl_xor_sync(0xffffffffu, sw, off);
    }
    float invx = 1.f / fmaxf(sx, 1e-9f);
    float invy = 1.f / fmaxf(sy, 1e-9f);
    float invz = 1.f / fmaxf(sz, 1e-9f);
    float invw = 1.f / fmaxf(sw, 1e-9f);

    float r0 = a0 * invx + resid[node * FDIM + 0  + lane] + bias[0  + lane];
    float r1 = a1 * invy + resid[node * FDIM + 32 + lane] + bias[32 + lane];
    float r2 = a2 * invz + resid[node * FDIM + 64 + lane] + bias[64 + lane];
    float r3 = a3 * invw + resid[node * FDIM + 96 + lane] + bias[96 + lane];

    if (MODE == 1) {
        out[node * FDIM + 0  + lane] = elu1(r0);
        out[node * FDIM + 32 + lane] = elu1(r1);
        out[node * FDIM + 64 + lane] = elu1(r2);
        out[node * FDIM + 96 + lane] = elu1(r3);
    } else {
        out[node * 32 + lane] = 0.25f * (r0 + r1 + r2 + r3);
    }
}

// -------------------- launch ------------------------------------------------
extern "C" void kernel_launch(void* const* d_in, const int* in_sizes, int n_in,
                              void* d_out, int out_size) {
    const float* x   = (const float*)d_in[0];
    const float* W1  = (const float*)d_in[1];
    const float* al1 = (const float*)d_in[2];
    const float* ar1 = (const float*)d_in[3];
    const float* b1  = (const float*)d_in[4];
    const float* W2  = (const float*)d_in[5];
    const float* al2 = (const float*)d_in[6];
    const float* ar2 = (const float*)d_in[7];
    const float* b2  = (const float*)d_in[8];
    const int*   src = (const int*)d_in[9];
    const int*   dst = (const int*)d_in[10];
    float* out = (float*)d_out;

    float* h1 = nullptr;
    cudaGetSymbolAddress((void**)&h1, g_h1);

    const int TB = 256;
    int nblkN = (NN + TB - 1) / TB;
    int nblkE = (EE + TB - 1) / TB;
    int nScan = (NN + 1023) / 1024;                 // 49
    int nAgg  = (NN + AGG_WARPS - 1) / AGG_WARPS;   // 6250
    int nGemm = (NN + GTM - 1) / GTM;               // 782

    // ---- CSR build (once; shared by both layers) ----
    k_zero_cnt<<<nblkN, TB>>>();
    k_count<<<nblkE, TB>>>(dst);
    k_scan1<<<nScan, 1024>>>();
    k_scan2<<<1, 64>>>(nScan);
    k_scan3<<<nblkN, TB>>>();
    k_scatter<<<nblkE, TB>>>(src, dst);

    // ---- layer 1 ----
    k_gemm_fused<<<nGemm, 256>>>(x, W1, al1, ar1);
    k_agg<1><<<nAgg, AGG_WARPS * 32>>>(x, b1, h1);

    // ---- layer 2 ----
    k_gemm_fused<<<nGemm, 256>>>(h1, W2, al2, ar2);
    k_agg<2><<<nAgg, AGG_WARPS * 32>>>(h1, b2, out);
}